// round 3
// baseline (speedup 1.0000x reference)
#include <cuda_runtime.h>

#define NN 4096
#define NJ 32                 // j-chunks (grid.y)
#define JCHUNK (NN / NJ)      // 128 j's per block
#define IBLK 256              // threads per block (one i per thread)
#define EPSF 1e-8f

// Deterministic partial repulsive-force accumulators: g_rf[chunk][i]
__device__ float2 g_rf[NJ][NN];

__device__ __forceinline__ float ex2a(float x) {
    float r; asm("ex2.approx.ftz.f32 %0, %1;" : "=f"(r) : "f"(x)); return r;
}
__device__ __forceinline__ float rsqa(float x) {
    float r; asm("rsqrt.approx.ftz.f32 %0, %1;" : "=f"(r) : "f"(x)); return r;
}

// ---------------------------------------------------------------------------
// Kernel 1: pairwise social forces.
// grid = (NN/IBLK, NJ); each block: 256 i's (one per thread) x 128 j's (smem).
// mag/d * diff with mag = ALPHA * exp((2*R - d)/BETA):
//   exp((0.6 - d)/0.71) * 10  ==  exp2( fma(d, -C1, C0) )
//   C1 = log2(e)/0.71 = 2.0319649,  C0 = 0.6*C1 + log2(10) = 4.5411070
// Diagonal (j==i): dx=dy=0 exactly -> contribution exactly 0, no branch needed.
// ---------------------------------------------------------------------------
__global__ __launch_bounds__(IBLK) void pair_kernel(const float4* __restrict__ state) {
    __shared__ float2 spos[JCHUNK];

    const int i     = blockIdx.x * IBLK + threadIdx.x;
    const int jbase = blockIdx.y * JCHUNK;

    if (threadIdx.x < JCHUNK) {
        float4 s = state[jbase + threadIdx.x];
        spos[threadIdx.x] = make_float2(s.x, s.y);
    }
    __syncthreads();

    const float4 si = state[i];
    const float xi = si.x, yi = si.y;

    const float C1 = 2.0319649f;
    const float C0 = 4.5411070f;

    float fx = 0.0f, fy = 0.0f;

#pragma unroll 8
    for (int jj = 0; jj < JCHUNK; jj++) {
        float2 pj = spos[jj];
        float dx = xi - pj.x;
        float dy = yi - pj.y;
        float t  = fmaf(dx, dx, EPSF);
        t        = fmaf(dy, dy, t);
        float inv = rsqa(t);          // 1/d
        float d   = t * inv;          // d = sqrt(d2 + eps)
        float e   = ex2a(fmaf(d, -C1, C0));   // ALPHA * exp((0.6-d)/0.71)
        float s   = e * inv;          // mag / d
        fx = fmaf(s, dx, fx);
        fy = fmaf(s, dy, fy);
    }

    g_rf[blockIdx.y][i] = make_float2(fx, fy);
}

// ---------------------------------------------------------------------------
// Kernel 2: reduce partials, attractive force, integrate, speed clamp,
// write out[i] = (pos_new, v_new).
// ---------------------------------------------------------------------------
__global__ __launch_bounds__(256) void finalize_kernel(const float4* __restrict__ state,
                                                       const float2* __restrict__ goals,
                                                       float4* __restrict__ out) {
    const int i = blockIdx.x * 256 + threadIdx.x;

    float fx = 0.0f, fy = 0.0f;
#pragma unroll
    for (int c = 0; c < NJ; c++) {
        float2 p = g_rf[c][i];
        fx += p.x; fy += p.y;
    }

    const float4 s = state[i];
    const float2 g = goals[i];

    float tx = g.x - s.x;
    float ty = g.y - s.y;
    float dist = sqrtf(fmaf(tx, tx, fmaf(ty, ty, EPSF)));
    float ds   = (i == 0) ? 1.0f : 1.4f;       // robot vs pedestrian speed
    float k    = ds / dist;

    float afx = 2.0f * (tx * k - s.z);          // K = 2
    float afy = 2.0f * (ty * k - s.w);

    float Fx = fx + afx;
    float Fy = fy + afy;

    float vnx = fmaf(Fx, 0.1f / 60.0f, s.z);    // vel + F/mass*dt
    float vny = fmaf(Fy, 0.1f / 60.0f, s.w);

    float sp = sqrtf(fmaf(vnx, vnx, fmaf(vny, vny, EPSF)));
    float sc = fminf(1.0f, 1.4f / sp);
    vnx *= sc; vny *= sc;

    float pnx = fmaf(vnx, 0.1f, s.x);
    float pny = fmaf(vny, 0.1f, s.y);

    out[i] = make_float4(pnx, pny, vnx, vny);
}

// ---------------------------------------------------------------------------
// Kernel 3: cost update (depends on out[0].xy = new robot pose).
// temp = 5*pg + 2*exp(-dist_r/1.5);  new_cost = cost + temp
// ---------------------------------------------------------------------------
__global__ __launch_bounds__(256) void cost_kernel(const float* __restrict__ cost_in,
                                                   const float* __restrict__ rip,
                                                   const float* __restrict__ goal,
                                                   const float4* __restrict__ outs,
                                                   float* __restrict__ cost_out) {
    const int i = blockIdx.x * 256 + threadIdx.x;

    const float4 r0 = outs[0];
    const float rx = r0.x, ry = r0.y;
    const float g0 = goal[0], g1 = goal[1];

    float a0 = rip[0] - g0, a1 = rip[1] - g1;
    float b0 = rx - g0,     b1 = ry - g1;
    float pg = sqrtf(fmaf(a0, a0, fmaf(a1, a1, EPSF)))
             - sqrtf(fmaf(b0, b0, fmaf(b1, b1, EPSF)));

    const float4 oi = outs[i];
    float dx = oi.x - rx, dy = oi.y - ry;
    float dr = sqrtf(fmaf(dx, dx, fmaf(dy, dy, EPSF)));

    // exp(-dr/1.5) = exp2(-dr * log2(e)/1.5)
    float e = ex2a(dr * (-1.4426950408889634f / 1.5f));

    cost_out[i] = cost_in[i] + fmaf(2.0f, e, 5.0f * pg);
}

// ---------------------------------------------------------------------------
// Launch. Inputs (metadata order): state[N,4], cost[N,1], goals[N,2],
// robot_init_pose[2], goal[2]. Output: out[N,4] then new_cost[N,1].
// ---------------------------------------------------------------------------
extern "C" void kernel_launch(void* const* d_in, const int* in_sizes, int n_in,
                              void* d_out, int out_size) {
    const float* state = (const float*)d_in[0];
    const float* cost  = (const float*)d_in[1];
    const float* goals = (const float*)d_in[2];
    const float* rip   = (const float*)d_in[3];
    const float* goal  = (const float*)d_in[4];
    float* out = (float*)d_out;

    dim3 grid1(NN / IBLK, NJ);
    pair_kernel<<<grid1, IBLK>>>((const float4*)state);
    finalize_kernel<<<NN / 256, 256>>>((const float4*)state, (const float2*)goals,
                                       (float4*)out);
    cost_kernel<<<NN / 256, 256>>>(cost, rip, goal, (const float4*)out,
                                   out + NN * 4);
}